// round 4
// baseline (speedup 1.0000x reference)
#include <cuda_runtime.h>
#include <math.h>

// Problem constants
#define NQ   64          // queries
#define DD   256         // feature dim
#define NS   4096        // bank size
#define IMG  65536       // C*H*W floats per image
#define FPB  32          // features per sim block
#define SIMBLOCKS (NS / FPB)   // 128

// smem layout for sim kernel (transposed, padded strides)
#define QS_STRIDE 68     // 64 rows + 4 pad  (keeps float4 alignment, kills conflicts)
#define FS_STRIDE 36     // 32 rows + 4 pad
#define QS_FLOATS (DD * QS_STRIDE)   // 17408
#define FS_FLOATS (DD * FS_STRIDE)   //  9216
#define SMEM_BYTES ((QS_FLOATS + FS_FLOATS) * 4 + NQ * 8 * 8)  // 110592 B

__device__ float g_qn[NQ * DD];                 // normalized queries
__device__ unsigned long long g_best[NQ];       // packed (ordered-float, ~idx)

// Map float to order-preserving uint32, pack with inverted index so that
// larger packed == (larger sim, or equal sim with smaller index).
__device__ __forceinline__ unsigned long long packkey(float f, unsigned idx) {
    unsigned u = __float_as_uint(f);
    u = (u & 0x80000000u) ? ~u : (u | 0x80000000u);
    return ((unsigned long long)u << 32) | (0xFFFFFFFFu - idx);
}

// ---------------------------------------------------------------------------
// Kernel 1: L2-normalize queries (matches F.normalize: x / max(||x||, 1e-12)),
// and reset the per-query argmax accumulators (must happen every graph replay).
// ---------------------------------------------------------------------------
__global__ void init_kernel(const float* __restrict__ q) {
    int b = blockIdx.x, t = threadIdx.x;
    float v = q[b * DD + t];
    float s = v * v;
    #pragma unroll
    for (int o = 16; o; o >>= 1) s += __shfl_xor_sync(0xffffffffu, s, o);
    __shared__ float ws[8];
    int w = t >> 5, l = t & 31;
    if (l == 0) ws[w] = s;
    __syncthreads();
    if (w == 0) {
        float x = ws[l & 7];
        #pragma unroll
        for (int o = 4; o; o >>= 1) x += __shfl_xor_sync(0xffffffffu, x, o);
        if (l == 0) ws[0] = x;
    }
    __syncthreads();
    float norm = fmaxf(sqrtf(ws[0]), 1e-12f);
    g_qn[b * DD + t] = v / norm;
    if (t == 0) g_best[b] = 0ull;   // below any real packed key
}

// ---------------------------------------------------------------------------
// Kernel 2: sim tile GEMM (64 queries x 32 features x K=256) + fused argmax.
// Grid 128 blocks x 128 threads. Features are read from DRAM exactly once.
// Thread (tx in [0,16), ty in [0,8)) computes a 4x4 register tile.
// ---------------------------------------------------------------------------
__global__ void __launch_bounds__(128, 1) sim_kernel(const float* __restrict__ feats) {
    extern __shared__ float sm[];
    float* qs = sm;                          // [256][68]  qs[k*68 + qrow]
    float* fs = sm + QS_FLOATS;              // [256][36]  fs[k*36 + frow]
    unsigned long long* red =
        (unsigned long long*)(sm + QS_FLOATS + FS_FLOATS);   // [64][8]

    const int tid = threadIdx.x;
    const int f0  = blockIdx.x * FPB;

    // Stage normalized q, transposed (coalesced global reads)
    for (int i = tid; i < NQ * DD; i += 128) {
        int r = i >> 8, k = i & 255;
        qs[k * QS_STRIDE + r] = g_qn[i];
    }
    // Stage this block's 32 feature rows, transposed
    for (int i = tid; i < FPB * DD; i += 128) {
        int r = i >> 8, k = i & 255;
        fs[k * FS_STRIDE + r] = feats[(size_t)(f0 + r) * DD + k];
    }
    __syncthreads();

    const int tx = tid & 15, ty = tid >> 4;
    float acc[4][4];
    #pragma unroll
    for (int i = 0; i < 4; i++)
        #pragma unroll
        for (int j = 0; j < 4; j++) acc[i][j] = 0.f;

    #pragma unroll 4
    for (int k = 0; k < DD; k++) {
        float4 a = *reinterpret_cast<const float4*>(&qs[k * QS_STRIDE + 4 * tx]);
        float4 b = *reinterpret_cast<const float4*>(&fs[k * FS_STRIDE + 4 * ty]);
        float av[4] = {a.x, a.y, a.z, a.w};
        float bv[4] = {b.x, b.y, b.z, b.w};
        #pragma unroll
        for (int i = 0; i < 4; i++)
            #pragma unroll
            for (int j = 0; j < 4; j++)
                acc[i][j] = fmaf(av[i], bv[j], acc[i][j]);
    }

    // Per-thread max over its 4 features (strict > keeps lowest index on tie)
    #pragma unroll
    for (int i = 0; i < 4; i++) {
        float m = acc[i][0]; int bj = 0;
        #pragma unroll
        for (int j = 1; j < 4; j++)
            if (acc[i][j] > m) { m = acc[i][j]; bj = j; }
        red[(4 * tx + i) * 8 + ty] = packkey(m, (unsigned)(f0 + 4 * ty + bj));
    }
    __syncthreads();

    // One thread per query reduces the 8 ty-partials, then global atomicMax
    if (tid < NQ) {
        unsigned long long p = red[tid * 8];
        #pragma unroll
        for (int j = 1; j < 8; j++) {
            unsigned long long v = red[tid * 8 + j];
            if (v > p) p = v;
        }
        atomicMax(&g_best[tid], p);
    }
}

// ---------------------------------------------------------------------------
// Kernel 3: gather selected images (float4 streaming copy) + write scores.
// Grid (16 chunks, 64 queries) x 256 threads; each block copies 16 KB.
// ---------------------------------------------------------------------------
__global__ void gather_kernel(const float* __restrict__ images,
                              float* __restrict__ out) {
    const int q = blockIdx.y;
    const unsigned long long p = g_best[q];
    const unsigned idx = 0xFFFFFFFFu - (unsigned)(p & 0xFFFFFFFFu);

    const float4* src = reinterpret_cast<const float4*>(images + (size_t)idx * IMG)
                        + blockIdx.x * 1024;
    float4* dst = reinterpret_cast<float4*>(out + (size_t)q * IMG)
                  + blockIdx.x * 1024;
    const int t = threadIdx.x;
    #pragma unroll
    for (int r = 0; r < 4; r++) dst[t + 256 * r] = src[t + 256 * r];

    if (blockIdx.x == 0 && t == 0) {
        unsigned u = (unsigned)(p >> 32);
        unsigned bits = (u & 0x80000000u) ? (u & 0x7FFFFFFFu) : ~u;
        out[(size_t)NQ * IMG + q] = __uint_as_float(bits);
    }
}

// ---------------------------------------------------------------------------
extern "C" void kernel_launch(void* const* d_in, const int* in_sizes, int n_in,
                              void* d_out, int out_size) {
    const float* q      = (const float*)d_in[0];   // (64, 256)
    const float* feats  = (const float*)d_in[1];   // (4096, 256), pre-normalized
    const float* images = (const float*)d_in[2];   // (4096, 1, 256, 256)
    float* out = (float*)d_out;                    // 64*65536 imgs + 64 scores

    // Idempotent, cheap; safe to call every launch (not a stream op).
    cudaFuncSetAttribute(sim_kernel,
                         cudaFuncAttributeMaxDynamicSharedMemorySize, SMEM_BYTES);

    init_kernel<<<NQ, DD>>>(q);
    sim_kernel<<<SIMBLOCKS, 128, SMEM_BYTES>>>(feats);
    gather_kernel<<<dim3(16, NQ), 256>>>(images, out);
}

// round 6
// speedup vs baseline: 1.0880x; 1.0880x over previous
#include <cuda_runtime.h>
#include <math.h>

// Problem constants
#define NQ   64          // queries
#define DD   256         // feature dim
#define NS   4096        // bank size
#define IMG  65536       // C*H*W floats per image
#define FPB  32          // features per sim block
#define SIMBLOCKS (NS / FPB)   // 128

// smem layout for sim kernel (transposed, padded strides)
#define QS_STRIDE 68     // 64 rows + 4 pad  (keeps float4 alignment, kills conflicts)
#define FS_STRIDE 36     // 32 rows + 4 pad
#define QS_FLOATS (DD * QS_STRIDE)   // 17408
#define FS_FLOATS (DD * FS_STRIDE)   //  9216
#define SMEM_BYTES ((QS_FLOATS + FS_FLOATS) * 4 + NQ * 8 * 8)  // 110592 B

// Per-(query, sim-block) partial argmax results. Every slot is rewritten on
// every replay -> no reset kernel, no atomics, fully deterministic.
__device__ unsigned long long g_part[NQ * SIMBLOCKS];

// Map float to order-preserving uint32, pack with inverted index so that
// larger packed == (larger sim, or equal sim with smaller index).
__device__ __forceinline__ unsigned long long packkey(float f, unsigned idx) {
    unsigned u = __float_as_uint(f);
    u = (u & 0x80000000u) ? ~u : (u | 0x80000000u);
    return ((unsigned long long)u << 32) | (0xFFFFFFFFu - idx);
}
__device__ __forceinline__ float unpackscore(unsigned long long p) {
    unsigned u = (unsigned)(p >> 32);
    unsigned bits = (u & 0x80000000u) ? (u & 0x7FFFFFFFu) : ~u;
    return __uint_as_float(bits);
}
__device__ __forceinline__ unsigned long long umax64(unsigned long long a,
                                                     unsigned long long b) {
    return a > b ? a : b;
}

// ---------------------------------------------------------------------------
// Kernel 1: sim tile GEMM (64 queries x 32 features x K=256) on RAW q + fused
// per-block argmax. argmax(q.F^T) == argmax(q_hat.F^T) since 1/||q|| > 0; the
// norm is applied to the winning score later. Features read from DRAM once.
// Grid 128 blocks x 128 threads; thread (tx in [0,16), ty in [0,8)) owns a
// 4x4 register tile.
// ---------------------------------------------------------------------------
__global__ void __launch_bounds__(128, 1) sim_kernel(const float* __restrict__ q,
                                                     const float* __restrict__ feats) {
    extern __shared__ float sm[];
    float* qs = sm;                          // [256][68]  qs[k*68 + qrow]
    float* fs = sm + QS_FLOATS;              // [256][36]  fs[k*36 + frow]
    unsigned long long* red =
        (unsigned long long*)(sm + QS_FLOATS + FS_FLOATS);   // [64][8]

    const int tid = threadIdx.x;
    const int f0  = blockIdx.x * FPB;

    // Stage raw q, transposed (coalesced global reads)
    for (int i = tid; i < NQ * DD; i += 128) {
        int r = i >> 8, k = i & 255;
        qs[k * QS_STRIDE + r] = q[i];
    }
    // Stage this block's 32 feature rows, transposed
    for (int i = tid; i < FPB * DD; i += 128) {
        int r = i >> 8, k = i & 255;
        fs[k * FS_STRIDE + r] = feats[(size_t)(f0 + r) * DD + k];
    }
    __syncthreads();

    const int tx = tid & 15, ty = tid >> 4;
    float acc[4][4];
    #pragma unroll
    for (int i = 0; i < 4; i++)
        #pragma unroll
        for (int j = 0; j < 4; j++) acc[i][j] = 0.f;

    #pragma unroll 4
    for (int k = 0; k < DD; k++) {
        float4 a = *reinterpret_cast<const float4*>(&qs[k * QS_STRIDE + 4 * tx]);
        float4 b = *reinterpret_cast<const float4*>(&fs[k * FS_STRIDE + 4 * ty]);
        float av[4] = {a.x, a.y, a.z, a.w};
        float bv[4] = {b.x, b.y, b.z, b.w};
        #pragma unroll
        for (int i = 0; i < 4; i++)
            #pragma unroll
            for (int j = 0; j < 4; j++)
                acc[i][j] = fmaf(av[i], bv[j], acc[i][j]);
    }

    // Per-thread max over its 4 features (strict > keeps lowest index on tie)
    #pragma unroll
    for (int i = 0; i < 4; i++) {
        float m = acc[i][0]; int bj = 0;
        #pragma unroll
        for (int j = 1; j < 4; j++)
            if (acc[i][j] > m) { m = acc[i][j]; bj = j; }
        red[(4 * tx + i) * 8 + ty] = packkey(m, (unsigned)(f0 + 4 * ty + bj));
    }
    __syncthreads();

    // One thread per query reduces the 8 ty-partials -> its private slot.
    if (tid < NQ) {
        unsigned long long p = red[tid * 8];
        #pragma unroll
        for (int j = 1; j < 8; j++) p = umax64(p, red[tid * 8 + j]);
        g_part[tid * SIMBLOCKS + blockIdx.x] = p;
    }
}

// ---------------------------------------------------------------------------
// Kernel 2: per-query final argmax reduce (redundant per block, L2-hot 1 KB)
// + image gather (float4 streaming copy) + normalized score write.
// Grid (16 chunks, 64 queries) x 256 threads; each block copies 16 KB.
// ---------------------------------------------------------------------------
__global__ void __launch_bounds__(256, 8) gather_kernel(const float* __restrict__ q,
                                                        const float* __restrict__ images,
                                                        float* __restrict__ out) {
    __shared__ unsigned long long sred[4];
    __shared__ unsigned long long sbest;

    const int qi = blockIdx.y;
    const int t  = threadIdx.x;

    // Reduce 128 per-block partials for this query.
    unsigned long long p = 0ull;
    if (t < SIMBLOCKS) p = g_part[qi * SIMBLOCKS + t];
    #pragma unroll
    for (int o = 16; o; o >>= 1)
        p = umax64(p, __shfl_xor_sync(0xffffffffu, p, o));
    if (t < SIMBLOCKS && (t & 31) == 0) sred[t >> 5] = p;
    __syncthreads();
    if (t == 0) {
        unsigned long long m = sred[0];
        #pragma unroll
        for (int j = 1; j < 4; j++) m = umax64(m, sred[j]);
        sbest = m;
    }
    __syncthreads();

    const unsigned long long best = sbest;
    const unsigned idx = 0xFFFFFFFFu - (unsigned)(best & 0xFFFFFFFFu);

    // Streaming copy of the selected image chunk.
    const float4* src = reinterpret_cast<const float4*>(images + (size_t)idx * IMG)
                        + blockIdx.x * 1024;
    float4* dst = reinterpret_cast<float4*>(out + (size_t)qi * IMG)
                  + blockIdx.x * 1024;
    #pragma unroll
    for (int r = 0; r < 4; r++) dst[t + 256 * r] = src[t + 256 * r];

    // Block (0, qi): compute ||q_qi|| with warp 0 and write normalized score.
    if (blockIdx.x == 0 && t < 32) {
        const float4* qr = reinterpret_cast<const float4*>(q + qi * DD);
        float s = 0.f;
        #pragma unroll
        for (int j = 0; j < 2; j++) {
            float4 v = qr[t + 32 * j];
            s += v.x * v.x + v.y * v.y + v.z * v.z + v.w * v.w;
        }
        #pragma unroll
        for (int o = 16; o; o >>= 1) s += __shfl_xor_sync(0xffffffffu, s, o);
        if (t == 0) {
            float norm = fmaxf(sqrtf(s), 1e-12f);
            out[(size_t)NQ * IMG + qi] = unpackscore(best) / norm;
        }
    }
}

// ---------------------------------------------------------------------------
extern "C" void kernel_launch(void* const* d_in, const int* in_sizes, int n_in,
                              void* d_out, int out_size) {
    const float* q      = (const float*)d_in[0];   // (64, 256)
    const float* feats  = (const float*)d_in[1];   // (4096, 256), pre-normalized
    const float* images = (const float*)d_in[2];   // (4096, 1, 256, 256)
    float* out = (float*)d_out;                    // 64*65536 imgs + 64 scores

    // Idempotent, cheap; host-side attribute set (not a stream op).
    cudaFuncSetAttribute(sim_kernel,
                         cudaFuncAttributeMaxDynamicSharedMemorySize, SMEM_BYTES);

    sim_kernel<<<SIMBLOCKS, 128, SMEM_BYTES>>>(q, feats);
    gather_kernel<<<dim3(16, NQ), 256>>>(q, images, out);
}

// round 7
// speedup vs baseline: 1.2076x; 1.1099x over previous
#include <cuda_runtime.h>
#include <math.h>

// Problem constants
#define NQ   64          // queries
#define DD   256         // feature dim
#define NS   4096        // bank size
#define IMG  65536       // C*H*W floats per image
#define FPB  32          // features per sim block
#define SIMBLOCKS (NS / FPB)   // 128

// smem layout for sim kernel (transposed, padded strides)
#define QS_STRIDE 68     // 64 rows + 4 pad (float4-aligned reads, conflict-free)
#define FS_STRIDE 36     // 32 rows + 4 pad
#define QS_FLOATS (DD * QS_STRIDE)   // 17408
#define FS_FLOATS (DD * FS_STRIDE)   //  9216
#define RED_SLOTS (NQ * 16)          // per-(query, ty) partials
#define SMEM_BYTES ((QS_FLOATS + FS_FLOATS) * 4 + RED_SLOTS * 8)  // 114688 B

// Per-(query, sim-block) partial argmax results. Every slot is rewritten on
// every replay -> no reset kernel, no atomics, fully deterministic.
__device__ unsigned long long g_part[NQ * SIMBLOCKS];

__device__ __forceinline__ unsigned long long packkey(float f, unsigned idx) {
    unsigned u = __float_as_uint(f);
    u = (u & 0x80000000u) ? ~u : (u | 0x80000000u);
    return ((unsigned long long)u << 32) | (0xFFFFFFFFu - idx);
}
__device__ __forceinline__ float unpackscore(unsigned long long p) {
    unsigned u = (unsigned)(p >> 32);
    unsigned bits = (u & 0x80000000u) ? (u & 0x7FFFFFFFu) : ~u;
    return __uint_as_float(bits);
}
__device__ __forceinline__ unsigned long long umax64(unsigned long long a,
                                                     unsigned long long b) {
    return a > b ? a : b;
}

// ---------------------------------------------------------------------------
// Kernel 1: sim tile GEMM (64 q x 32 f x K=256) on RAW q + fused argmax.
// argmax(q.F^T) == argmax(q_hat.F^T) since 1/||q|| > 0; norm applied at
// score-write time. 256 threads (8 warps = 2/SMSP), thread tile 4x2.
// Staging uses a 4-rows x 8-ks lane remap: STS bank = (4*dk + dr + 4*rb) % 32
// is a permutation of the warp -> conflict-free transposed stores.
// ---------------------------------------------------------------------------
__global__ void __launch_bounds__(256, 1) sim_kernel(const float* __restrict__ q,
                                                     const float* __restrict__ feats) {
    extern __shared__ float sm[];
    float* qs = sm;                          // [256][68]  qs[k*68 + qrow]
    float* fs = sm + QS_FLOATS;              // [256][36]  fs[k*36 + frow]
    unsigned long long* red =
        (unsigned long long*)(sm + QS_FLOATS + FS_FLOATS);   // [64][16]

    const int tid  = threadIdx.x;
    const int lane = tid & 31;
    const int warp = tid >> 5;               // 8 warps
    const int f0   = blockIdx.x * FPB;

    const int dr = lane >> 3;                // 0..3  row within 4-row group
    const int dk = lane & 7;                 // 0..7  k within 8-k group

    // Stage raw q transposed: 512 groups of (4 rows x 8 ks), 64 per warp.
    #pragma unroll 4
    for (int g = warp; g < 512; g += 8) {
        int rb = g & 15, kb = g >> 4;        // 16 row-blocks x 32 k-blocks
        int r = rb * 4 + dr, k = kb * 8 + dk;
        qs[k * QS_STRIDE + r] = q[r * DD + k];
    }
    // Stage this block's 32 feature rows transposed: 256 groups, 32 per warp.
    #pragma unroll 4
    for (int g = warp; g < 256; g += 8) {
        int rb = g & 7, kb = g >> 3;         // 8 row-blocks x 32 k-blocks
        int r = rb * 4 + dr, k = kb * 8 + dk;
        fs[k * FS_STRIDE + r] = feats[(size_t)(f0 + r) * DD + k];
    }
    __syncthreads();

    const int tx = tid & 15;                 // q rows 4tx..4tx+3
    const int ty = tid >> 4;                 // f cols 2ty, 2ty+1
    float acc[4][2];
    #pragma unroll
    for (int i = 0; i < 4; i++) { acc[i][0] = 0.f; acc[i][1] = 0.f; }

    #pragma unroll 8
    for (int k = 0; k < DD; k++) {
        float4 a = *reinterpret_cast<const float4*>(&qs[k * QS_STRIDE + 4 * tx]);
        float2 b = *reinterpret_cast<const float2*>(&fs[k * FS_STRIDE + 2 * ty]);
        float av[4] = {a.x, a.y, a.z, a.w};
        #pragma unroll
        for (int i = 0; i < 4; i++) {
            acc[i][0] = fmaf(av[i], b.x, acc[i][0]);
            acc[i][1] = fmaf(av[i], b.y, acc[i][1]);
        }
    }

    // Per-thread max over its 2 features (strict > keeps lowest index on tie)
    #pragma unroll
    for (int i = 0; i < 4; i++) {
        float m = acc[i][0]; int bj = 0;
        if (acc[i][1] > m) { m = acc[i][1]; bj = 1; }
        red[(4 * tx + i) * 16 + ty] = packkey(m, (unsigned)(f0 + 2 * ty + bj));
    }
    __syncthreads();

    // One thread per query reduces the 16 ty-partials -> its private slot.
    if (tid < NQ) {
        unsigned long long p = red[tid * 16];
        #pragma unroll
        for (int j = 1; j < 16; j++) p = umax64(p, red[tid * 16 + j]);
        g_part[tid * SIMBLOCKS + blockIdx.x] = p;
    }
}

// ---------------------------------------------------------------------------
// Kernel 2: per-query final argmax reduce (redundant per block, L2-hot 1 KB)
// + image gather + normalized score write.
// Grid (8 chunks, 64 queries) x 256 threads; each block copies 32 KB with
// 8 independent float4 loads in flight per thread.
// ---------------------------------------------------------------------------
__global__ void __launch_bounds__(256, 8) gather_kernel(const float* __restrict__ q,
                                                        const float* __restrict__ images,
                                                        float* __restrict__ out) {
    __shared__ unsigned long long sred[4];
    __shared__ unsigned long long sbest;

    const int qi = blockIdx.y;
    const int t  = threadIdx.x;

    // Reduce 128 per-block partials for this query.
    unsigned long long p = 0ull;
    if (t < SIMBLOCKS) p = g_part[qi * SIMBLOCKS + t];
    #pragma unroll
    for (int o = 16; o; o >>= 1)
        p = umax64(p, __shfl_xor_sync(0xffffffffu, p, o));
    if (t < SIMBLOCKS && (t & 31) == 0) sred[t >> 5] = p;
    __syncthreads();
    if (t == 0) {
        unsigned long long m = sred[0];
        #pragma unroll
        for (int j = 1; j < 4; j++) m = umax64(m, sred[j]);
        sbest = m;
    }
    __syncthreads();

    const unsigned long long best = sbest;
    const unsigned idx = 0xFFFFFFFFu - (unsigned)(best & 0xFFFFFFFFu);

    // Streaming copy: 32 KB per block, loads batched before stores for MLP.
    const float4* src = reinterpret_cast<const float4*>(images + (size_t)idx * IMG)
                        + (size_t)blockIdx.x * 2048;
    float4* dst = reinterpret_cast<float4*>(out + (size_t)qi * IMG)
                  + (size_t)blockIdx.x * 2048;
    float4 v[8];
    #pragma unroll
    for (int r = 0; r < 8; r++) v[r] = src[t + 256 * r];
    #pragma unroll
    for (int r = 0; r < 8; r++) dst[t + 256 * r] = v[r];

    // Block (0, qi): compute ||q_qi|| with warp 0 and write normalized score.
    if (blockIdx.x == 0 && t < 32) {
        const float4* qr = reinterpret_cast<const float4*>(q + qi * DD);
        float s = 0.f;
        #pragma unroll
        for (int j = 0; j < 2; j++) {
            float4 w = qr[t + 32 * j];
            s += w.x * w.x + w.y * w.y + w.z * w.z + w.w * w.w;
        }
        #pragma unroll
        for (int o = 16; o; o >>= 1) s += __shfl_xor_sync(0xffffffffu, s, o);
        if (t == 0) {
            float norm = fmaxf(sqrtf(s), 1e-12f);
            out[(size_t)NQ * IMG + qi] = unpackscore(best) / norm;
        }
    }
}

// ---------------------------------------------------------------------------
extern "C" void kernel_launch(void* const* d_in, const int* in_sizes, int n_in,
                              void* d_out, int out_size) {
    const float* q      = (const float*)d_in[0];   // (64, 256)
    const float* feats  = (const float*)d_in[1];   // (4096, 256), pre-normalized
    const float* images = (const float*)d_in[2];   // (4096, 1, 256, 256)
    float* out = (float*)d_out;                    // 64*65536 imgs + 64 scores

    cudaFuncSetAttribute(sim_kernel,
                         cudaFuncAttributeMaxDynamicSharedMemorySize, SMEM_BYTES);

    sim_kernel<<<SIMBLOCKS, 256, SMEM_BYTES>>>(q, feats);
    gather_kernel<<<dim3(8, NQ), 256>>>(q, images, out);
}